// round 6
// baseline (speedup 1.0000x reference)
#include <cuda_runtime.h>
#include <cuda_bf16.h>
#include <math.h>

#define NQ   16384
#define NF   8192
#define DD   64
#define TOPK 32
#define KNN  5

#define BM 128
#define BN 128
#define PADQ 132                       // floats per feature row (33 float4s, odd -> conflict-free)
#define SMEM_BYTES (2 * 64 * PADQ * 4) // 67584 bytes dynamic

// ---------------- scratch (__device__ globals; no runtime allocation) -------
__device__ float g_Xc[(size_t)NQ * DD];
__device__ float g_Fc[(size_t)NF * DD];
__device__ float g_SqX[NQ];
__device__ float g_SqF[NF];
__device__ unsigned long long g_qbits[NQ];
__device__ unsigned long long g_fbits[NF];
__device__ float g_key[(size_t)NQ * NF];      // 512 MB distance-key matrix
__device__ int   g_topIdx[(size_t)NQ * TOPK];
__device__ float g_colmean[DD];

__device__ __forceinline__ float f_inf() { return __int_as_float(0x7f800000); }

// ---------------- packed fp32x2 helpers (sm_103a) ----------------------------
__device__ __forceinline__ unsigned long long pk2(float a, float b) {
    unsigned long long r;
    asm("mov.b64 %0, {%1, %2};" : "=l"(r) : "f"(a), "f"(b));
    return r;
}
__device__ __forceinline__ unsigned long long fma2(unsigned long long a,
                                                   unsigned long long b,
                                                   unsigned long long c) {
    unsigned long long d;
    asm("fma.rn.f32x2 %0, %1, %2, %3;" : "=l"(d) : "l"(a), "l"(b), "l"(c));
    return d;
}
__device__ __forceinline__ void upk2(unsigned long long v, float& a, float& b) {
    asm("mov.b64 {%0, %1}, %2;" : "=f"(a), "=f"(b) : "l"(v));
}

// ---------------- prep: clean values, observed bitmask, sum of squares ------
__global__ void prep_kernel(const float* __restrict__ src, int nrows, int isX)
{
    int w    = (blockIdx.x * blockDim.x + threadIdx.x) >> 5;
    int lane = threadIdx.x & 31;
    if (w >= nrows) return;

    float* clean             = isX ? g_Xc : g_Fc;
    float* sq                = isX ? g_SqX : g_SqF;
    unsigned long long* bits = isX ? g_qbits : g_fbits;

    const float* row = src + (size_t)w * DD;
    float v0 = row[lane];
    float v1 = row[lane + 32];
    bool  o0 = !isnan(v0);
    bool  o1 = !isnan(v1);
    float c0 = o0 ? v0 : 0.0f;
    float c1 = o1 ? v1 : 0.0f;
    clean[(size_t)w * DD + lane]      = c0;
    clean[(size_t)w * DD + lane + 32] = c1;

    unsigned ob0 = __ballot_sync(0xffffffffu, o0);
    unsigned ob1 = __ballot_sync(0xffffffffu, o1);

    float s = c0 * c0 + c1 * c1;
    #pragma unroll
    for (int o = 16; o > 0; o >>= 1) s += __shfl_xor_sync(0xffffffffu, s, o);

    if (lane == 0) {
        bits[w] = (unsigned long long)ob0 | ((unsigned long long)ob1 << 32);
        sq[w]   = s;
    }
}

// ---------------- per-column mean of observed fit values (fallback) ---------
__global__ void colmean_kernel(const float* __restrict__ fit)
{
    int c   = blockIdx.x;
    int tid = threadIdx.x;
    float s = 0.0f;
    int   n = 0;
    for (int r = tid; r < NF; r += 256) {
        float v = fit[(size_t)r * DD + c];
        if (!isnan(v)) { s += v; n++; }
    }
    __shared__ float ss[256];
    __shared__ int   sn[256];
    ss[tid] = s; sn[tid] = n;
    __syncthreads();
    for (int o = 128; o > 0; o >>= 1) {
        if (tid < o) { ss[tid] += ss[tid + o]; sn[tid] += sn[tid + o]; }
        __syncthreads();
    }
    if (tid == 0) g_colmean[c] = (sn[0] > 0) ? ss[0] / (float)sn[0] : 0.0f;
}

// ---------------- distance-key kernel: GEMM + sparse mask corrections -------
// key[q][r] = max(SqX+SqF-2*s - corrB - corrC, 0) * 64/cnt ; +inf if cnt==0
// Thread tile: rows {4ty..4ty+3, 64+4ty..}, cols {4tx..4tx+3, 64+4tx..}
__global__ __launch_bounds__(256) void dist_kernel()
{
    extern __shared__ float sm[];
    float* Xs = sm;                 // [64][PADQ] feature-major query tile
    float* Ys = sm + 64 * PADQ;     // [64][PADQ] feature-major fit tile
    __shared__ unsigned long long sQb[BM];
    __shared__ unsigned long long sFb[BN];

    int tid = threadIdx.x;
    int tx = tid & 15;
    int ty = tid >> 4;
    int qbase = blockIdx.y * BM;
    int rbase = blockIdx.x * BN;

    // stage tiles, transposed to feature-major, via coalesced LDG + STS.128
    #pragma unroll
    for (int it = 0; it < 8; ++it) {
        int e  = tid + it * 256;          // 0..2047
        int f  = e & 63;
        int q4 = (e >> 6) << 2;           // 0,4,...,124
        const float* gx = g_Xc + (size_t)(qbase + q4) * DD + f;
        const float* gf = g_Fc + (size_t)(rbase + q4) * DD + f;
        float4 v, w;
        v.x = gx[0]; v.y = gx[DD]; v.z = gx[2 * DD]; v.w = gx[3 * DD];
        w.x = gf[0]; w.y = gf[DD]; w.z = gf[2 * DD]; w.w = gf[3 * DD];
        *(float4*)&Xs[f * PADQ + q4] = v;
        *(float4*)&Ys[f * PADQ + q4] = w;
    }
    if (tid < BM) sQb[tid] = g_qbits[qbase + tid];
    else if (tid < BM + BN) sFb[tid - BM] = g_fbits[rbase + tid - BM];
    __syncthreads();

    const float4* X4 = (const float4*)Xs;   // row f = 33 float4s
    const float4* Y4 = (const float4*)Ys;

    unsigned long long acc2[8][4];
    #pragma unroll
    for (int i = 0; i < 8; i++)
        #pragma unroll
        for (int j = 0; j < 4; j++) acc2[i][j] = 0ull;

    // main dot product: s = sum_f x*y  (packed f32x2, 2 cols per op)
    #pragma unroll 8
    for (int f = 0; f < DD; ++f) {
        float4 xa = X4[f * 33 + ty];
        float4 xb = X4[f * 33 + 16 + ty];
        float4 ya = Y4[f * 33 + tx];
        float4 yb = Y4[f * 33 + 16 + tx];
        unsigned long long y01 = pk2(ya.x, ya.y);
        unsigned long long y23 = pk2(ya.z, ya.w);
        unsigned long long y45 = pk2(yb.x, yb.y);
        unsigned long long y67 = pk2(yb.z, yb.w);
        float xs[8] = {xa.x, xa.y, xa.z, xa.w, xb.x, xb.y, xb.z, xb.w};
        #pragma unroll
        for (int i = 0; i < 8; ++i) {
            unsigned long long xx = pk2(xs[i], xs[i]);
            acc2[i][0] = fma2(xx, y01, acc2[i][0]);
            acc2[i][1] = fma2(xx, y23, acc2[i][1]);
            acc2[i][2] = fma2(xx, y45, acc2[i][2]);
            acc2[i][3] = fma2(xx, y67, acc2[i][3]);
        }
    }

    // unpack and transform to d2 = SqX + SqF - 2*s
    float acc[8][8];
    {
        float sqx[8], sqf[8];
        #pragma unroll
        for (int i = 0; i < 8; i++) {
            int row = (i < 4) ? 4 * ty + i : 60 + 4 * ty + i;
            sqx[i] = g_SqX[qbase + row];
        }
        #pragma unroll
        for (int j = 0; j < 8; j++) {
            int col = (j < 4) ? 4 * tx + j : 60 + 4 * tx + j;
            sqf[j] = g_SqF[rbase + col];
        }
        #pragma unroll
        for (int i = 0; i < 8; i++) {
            #pragma unroll
            for (int p = 0; p < 4; p++) {
                float a, b;
                upk2(acc2[i][p], a, b);
                acc[i][2 * p]     = sqx[i] + sqf[2 * p]     - 2.0f * a;
                acc[i][2 * p + 1] = sqx[i] + sqf[2 * p + 1] - 2.0f * b;
            }
        }
    }

    // correction B: subtract x^2 at fit-row-missing features
    #pragma unroll
    for (int j = 0; j < 8; ++j) {
        int col = (j < 4) ? 4 * tx + j : 60 + 4 * tx + j;
        unsigned long long fb = sFb[col];
        unsigned mlo = ~(unsigned)fb;
        unsigned mhi = ~(unsigned)(fb >> 32);
        while (mlo) {
            int f = __ffs(mlo) - 1; mlo &= mlo - 1;
            float4 xa = X4[f * 33 + ty];
            float4 xb = X4[f * 33 + 16 + ty];
            acc[0][j] = fmaf(-xa.x, xa.x, acc[0][j]);
            acc[1][j] = fmaf(-xa.y, xa.y, acc[1][j]);
            acc[2][j] = fmaf(-xa.z, xa.z, acc[2][j]);
            acc[3][j] = fmaf(-xa.w, xa.w, acc[3][j]);
            acc[4][j] = fmaf(-xb.x, xb.x, acc[4][j]);
            acc[5][j] = fmaf(-xb.y, xb.y, acc[5][j]);
            acc[6][j] = fmaf(-xb.z, xb.z, acc[6][j]);
            acc[7][j] = fmaf(-xb.w, xb.w, acc[7][j]);
        }
        while (mhi) {
            int f = 32 + __ffs(mhi) - 1; mhi &= mhi - 1;
            float4 xa = X4[f * 33 + ty];
            float4 xb = X4[f * 33 + 16 + ty];
            acc[0][j] = fmaf(-xa.x, xa.x, acc[0][j]);
            acc[1][j] = fmaf(-xa.y, xa.y, acc[1][j]);
            acc[2][j] = fmaf(-xa.z, xa.z, acc[2][j]);
            acc[3][j] = fmaf(-xa.w, xa.w, acc[3][j]);
            acc[4][j] = fmaf(-xb.x, xb.x, acc[4][j]);
            acc[5][j] = fmaf(-xb.y, xb.y, acc[5][j]);
            acc[6][j] = fmaf(-xb.z, xb.z, acc[6][j]);
            acc[7][j] = fmaf(-xb.w, xb.w, acc[7][j]);
        }
    }
    // correction C: subtract y^2 at query-row-missing features
    #pragma unroll
    for (int i = 0; i < 8; ++i) {
        int row = (i < 4) ? 4 * ty + i : 60 + 4 * ty + i;
        unsigned long long qb = sQb[row];
        unsigned mlo = ~(unsigned)qb;
        unsigned mhi = ~(unsigned)(qb >> 32);
        while (mlo) {
            int f = __ffs(mlo) - 1; mlo &= mlo - 1;
            float4 ya = Y4[f * 33 + tx];
            float4 yb = Y4[f * 33 + 16 + tx];
            acc[i][0] = fmaf(-ya.x, ya.x, acc[i][0]);
            acc[i][1] = fmaf(-ya.y, ya.y, acc[i][1]);
            acc[i][2] = fmaf(-ya.z, ya.z, acc[i][2]);
            acc[i][3] = fmaf(-ya.w, ya.w, acc[i][3]);
            acc[i][4] = fmaf(-yb.x, yb.x, acc[i][4]);
            acc[i][5] = fmaf(-yb.y, yb.y, acc[i][5]);
            acc[i][6] = fmaf(-yb.z, yb.z, acc[i][6]);
            acc[i][7] = fmaf(-yb.w, yb.w, acc[i][7]);
        }
        while (mhi) {
            int f = 32 + __ffs(mhi) - 1; mhi &= mhi - 1;
            float4 ya = Y4[f * 33 + tx];
            float4 yb = Y4[f * 33 + 16 + tx];
            acc[i][0] = fmaf(-ya.x, ya.x, acc[i][0]);
            acc[i][1] = fmaf(-ya.y, ya.y, acc[i][1]);
            acc[i][2] = fmaf(-ya.z, ya.z, acc[i][2]);
            acc[i][3] = fmaf(-ya.w, ya.w, acc[i][3]);
            acc[i][4] = fmaf(-yb.x, yb.x, acc[i][4]);
            acc[i][5] = fmaf(-yb.y, yb.y, acc[i][5]);
            acc[i][6] = fmaf(-yb.z, yb.z, acc[i][6]);
            acc[i][7] = fmaf(-yb.w, yb.w, acc[i][7]);
        }
    }

    // finalize + store (2 x STG.128 per row)
    unsigned flo[8], fhi[8];
    #pragma unroll
    for (int j = 0; j < 8; j++) {
        int col = (j < 4) ? 4 * tx + j : 60 + 4 * tx + j;
        unsigned long long fb = sFb[col];
        flo[j] = (unsigned)fb;
        fhi[j] = (unsigned)(fb >> 32);
    }
    #pragma unroll
    for (int i = 0; i < 8; i++) {
        int row = (i < 4) ? 4 * ty + i : 60 + 4 * ty + i;
        unsigned long long qb = sQb[row];
        unsigned qlo = (unsigned)qb, qhi = (unsigned)(qb >> 32);
        float k[8];
        #pragma unroll
        for (int j = 0; j < 8; j++) {
            int n = __popc(qlo & flo[j]) + __popc(qhi & fhi[j]);
            float d2 = fmaxf(acc[i][j], 0.0f) * 64.0f;      // *64 exact
            k[j] = (n > 0) ? __fdividef(d2, (float)n) : f_inf();
        }
        size_t rowoff = (size_t)(qbase + row) * NF + rbase;
        float4 o0 = {k[0], k[1], k[2], k[3]};
        float4 o1 = {k[4], k[5], k[6], k[7]};
        *(float4*)&g_key[rowoff + 4 * tx]      = o0;
        *(float4*)&g_key[rowoff + 64 + 4 * tx] = o1;
    }
}

// ---------------- top-32 per query ------------------------------------------
__global__ __launch_bounds__(256) void topk_kernel()
{
    int q = blockIdx.x;
    const float* row = g_key + (size_t)q * NF;
    int tid  = threadIdx.x;
    int lane = tid & 31;
    int w    = tid >> 5;

    unsigned bd[8];
    int      bi[8];
    #pragma unroll
    for (int j = 0; j < 8; j++) { bd[j] = 0xFFFFFFFFu; bi[j] = -1; }

    #pragma unroll 4
    for (int k = 0; k < NF / 256; k++) {
        int r = tid + (k << 8);
        unsigned v = __float_as_uint(row[r]);
        if (v < bd[7]) {
            bd[7] = v; bi[7] = r;
            #pragma unroll
            for (int j = 7; j > 0; --j) {
                if (bd[j] < bd[j - 1]) {
                    unsigned tv = bd[j]; bd[j] = bd[j - 1]; bd[j - 1] = tv;
                    int      ti = bi[j]; bi[j] = bi[j - 1]; bi[j - 1] = ti;
                }
            }
        }
    }

    __shared__ unsigned sv[8 * 32];
    __shared__ int      si[8 * 32];
    {
        int ptr = 0;
        unsigned head = bd[0];
        for (int r = 0; r < 32; r++) {
            unsigned m   = __reduce_min_sync(0xffffffffu, head);
            unsigned bal = __ballot_sync(0xffffffffu, head == m);
            int leader   = __ffs(bal) - 1;
            if (lane == leader) {
                sv[w * 32 + r] = m;
                si[w * 32 + r] = bi[ptr];
                ptr++;
                head = (ptr < 8) ? bd[ptr] : 0xFFFFFFFFu;
            }
        }
    }
    __syncthreads();

    if (w == 0) {
        unsigned cd[8];
        int      ci[8];
        int src = (lane & 7) * 32 + (lane >> 3) * 8;
        #pragma unroll
        for (int j = 0; j < 8; j++) { cd[j] = sv[src + j]; ci[j] = si[src + j]; }
        int ptr = 0;
        unsigned head = cd[0];
        for (int r = 0; r < 32; r++) {
            unsigned m   = __reduce_min_sync(0xffffffffu, head);
            unsigned bal = __ballot_sync(0xffffffffu, head == m);
            int leader   = __ffs(bal) - 1;
            if (lane == leader) {
                g_topIdx[(size_t)q * TOPK + r] = (m < 0x7f800000u) ? ci[ptr] : -1;
                ptr++;
                head = (ptr < 8) ? cd[ptr] : 0xFFFFFFFFu;
            }
        }
    }
}

// ---------------- impute: warp per query, 2 features per lane ---------------
__global__ void impute_kernel(const float* __restrict__ X, float* __restrict__ out)
{
    int q    = blockIdx.x * (blockDim.x >> 5) + (threadIdx.x >> 5);
    int lane = threadIdx.x & 31;
    if (q >= NQ) return;

    int myidx = g_topIdx[(size_t)q * TOPK + lane];

    float v0 = X[(size_t)q * DD + lane];
    float v1 = X[(size_t)q * DD + lane + 32];
    bool  n0 = isnan(v0);
    bool  n1 = isnan(v1);
    float s0 = 0.0f, s1 = 0.0f;
    int   c0 = 0, c1 = 0;

    for (int r = 0; r < TOPK; r++) {
        int i = __shfl_sync(0xffffffffu, myidx, r);
        if (i < 0) break;
        unsigned long long fb = g_fbits[i];
        if (n0 && c0 < KNN && ((fb >> lane) & 1ull)) {
            s0 += g_Fc[(size_t)i * DD + lane]; c0++;
        }
        if (n1 && c1 < KNN && ((fb >> (lane + 32)) & 1ull)) {
            s1 += g_Fc[(size_t)i * DD + lane + 32]; c1++;
        }
        bool done = (!n0 || c0 >= KNN) && (!n1 || c1 >= KNN);
        if (__all_sync(0xffffffffu, done)) break;
    }

    out[(size_t)q * DD + lane]      = n0 ? (c0 ? s0 / (float)c0 : g_colmean[lane])      : v0;
    out[(size_t)q * DD + lane + 32] = n1 ? (c1 ? s1 / (float)c1 : g_colmean[lane + 32]) : v1;
}

// ---------------- launcher ---------------------------------------------------
extern "C" void kernel_launch(void* const* d_in, const int* in_sizes, int n_in,
                              void* d_out, int out_size)
{
    const float* X   = (const float*)d_in[0];
    const float* fit = (const float*)d_in[1];
    float* out = (float*)d_out;
    (void)in_sizes; (void)n_in; (void)out_size;

    cudaFuncSetAttribute(dist_kernel,
                         cudaFuncAttributeMaxDynamicSharedMemorySize, SMEM_BYTES);

    prep_kernel<<<NQ / 8, 256>>>(X, NQ, 1);
    prep_kernel<<<NF / 8, 256>>>(fit, NF, 0);
    colmean_kernel<<<DD, 256>>>(fit);

    dim3 dgrid(NF / BN, NQ / BM);
    dist_kernel<<<dgrid, 256, SMEM_BYTES>>>();

    topk_kernel<<<NQ, 256>>>();

    impute_kernel<<<NQ / 8, 256>>>(X, out);
}